// round 4
// baseline (speedup 1.0000x reference)
#include <cuda_runtime.h>

#define NN 100000
#define NE 1250000
#define DD 64
#define NB_SCAN 98   // ceil(NN/1024)

// ---------------- scratch (static device globals; no allocation) ----------------
__device__ int   g_is64;
__device__ int   g_count[NN];
__device__ int   g_wcount[NN];
__device__ int   g_rowptr[NN + 1];
__device__ int   g_bsum[128];
__device__ int   g_boff[128];
__device__ float g_dinv[NN];
__device__ int2  g_csr[NE];              // {src, weight-as-int}
__device__ float g_hw[NN * DD];          // h @ W
__device__ float g_agg[NN * DD];         // aggregated (pre-BN)
__device__ float g_colsum[DD * 32];      // 128B-strided slots -> spread L2 slices
__device__ float g_colsq[DD * 32];
__device__ float g_scaleA[DD];
__device__ float g_shiftB[DD];

// ---------------- dtype detection ----------------
// If edge_index is int64 (values < 2^31, nonneg), every odd 32-bit word of the
// buffer is 0. Sample the first 2048 odd words; all-zero => int64 layout.
__global__ void k_detect(const int* __restrict__ ei) {
    __shared__ int cnt;
    if (threadIdx.x == 0) cnt = 0;
    __syncthreads();
    int nz = 0;
#pragma unroll
    for (int i = 0; i < 8; i++) {
        int pos = 2 * (threadIdx.x + i * 256) + 1;   // odd words, first 16KB
        if (ei[pos] != 0) nz = 1;
    }
    if (nz) atomicAdd(&cnt, 1);
    __syncthreads();
    if (threadIdx.x == 0) g_is64 = (cnt == 0) ? 1 : 0;
}

__device__ __forceinline__ int load_idx(const void* ei, long long pos) {
    if (g_is64) return (int)((const long long*)ei)[pos];
    return ((const int*)ei)[pos];
}

// ---------------- setup kernels ----------------
__global__ void k_zero_counts() {
    int i = blockIdx.x * blockDim.x + threadIdx.x;
    if (i < NN) { g_count[i] = 0; g_wcount[i] = 0; }
}

__global__ void k_degree(const void* __restrict__ ei) {
    int e = blockIdx.x * blockDim.x + threadIdx.x;
    if (e < NE) {
        int d = load_idx(ei, (long long)NE + e);   // dst row
        if ((unsigned)d < NN) atomicAdd(&g_count[d], 1);
    }
}

__global__ void k_dinv() {
    int i = blockIdx.x * blockDim.x + threadIdx.x;
    if (i < NN) g_dinv[i] = rsqrtf((float)(g_count[i] + 1));  // +1 self loop
}

__global__ void k_scan1() {
    __shared__ int sm[1024];
    int tid = threadIdx.x;
    int i = blockIdx.x * 1024 + tid;
    int v = (i < NN) ? g_count[i] : 0;
    sm[tid] = v;
    for (int off = 1; off < 1024; off <<= 1) {
        __syncthreads();
        int t = (tid >= off) ? sm[tid - off] : 0;
        __syncthreads();
        sm[tid] += t;
    }
    if (i < NN) g_rowptr[i] = sm[tid] - v;       // exclusive within block
    if (tid == 1023) g_bsum[blockIdx.x] = sm[1023];
}

__global__ void k_scan2() {
    __shared__ int sm[128];
    int tid = threadIdx.x;
    int v = (tid < NB_SCAN) ? g_bsum[tid] : 0;
    sm[tid] = v;
    for (int off = 1; off < 128; off <<= 1) {
        __syncthreads();
        int t = (tid >= off) ? sm[tid - off] : 0;
        __syncthreads();
        sm[tid] += t;
    }
    g_boff[tid] = sm[tid] - v;
}

__global__ void k_scan3() {
    int i = blockIdx.x * blockDim.x + threadIdx.x;
    if (i < NN) g_rowptr[i] += g_boff[i >> 10];
    if (i == 0) g_rowptr[NN] = 0;  // fixed below: set to total via last prefix
}

__global__ void k_rowptr_end() {
    // total edges counted = rowptr[NN-1] + count[NN-1]
    g_rowptr[NN] = g_rowptr[NN - 1] + g_count[NN - 1];
}

__global__ void k_fill(const void* __restrict__ ei) {
    int e = blockIdx.x * blockDim.x + threadIdx.x;
    if (e >= NE) return;
    int s = load_idx(ei, e);
    int d = load_idx(ei, (long long)NE + e);
    if ((unsigned)s >= NN || (unsigned)d >= NN) return;
    float w = g_dinv[s] * g_dinv[d];
    int p = g_rowptr[d] + atomicAdd(&g_wcount[d], 1);
    if ((unsigned)p < NE) g_csr[p] = make_int2(s, __float_as_int(w));
}

// ---------------- per-layer kernels ----------------
__global__ __launch_bounds__(256) void k_gemm(const float* __restrict__ x,
                                              const float* __restrict__ W, int layer) {
    __shared__ float Wsm[DD * DD];
    __shared__ float Ism[DD * DD];
    __shared__ float As[DD], Bs[DD];
    int tid = threadIdx.x;
    const float* gin = (layer == 0) ? x : g_agg;
    int bn = (layer > 0);
    if (bn) {
        if (tid < 64) { As[tid] = g_scaleA[tid]; Bs[tid] = g_shiftB[tid]; }
        __syncthreads();
    }
    int row0 = blockIdx.x * 64;
#pragma unroll
    for (int i = 0; i < 16; i++) {
        int idx = tid + i * 256;
        Wsm[idx] = W[idx];
        int r = idx >> 6, c = idx & 63;
        int gr = row0 + r;
        float v = 0.f;
        if (gr < NN) {
            v = gin[gr * DD + c];
            if (bn) v = fmaxf(fmaf(v, As[c], Bs[c]), 0.f);
        }
        Ism[idx] = v;
    }
    __syncthreads();

    int tx = tid & 15, ty = tid >> 4;
    float4 a0 = {0, 0, 0, 0}, a1 = a0, a2 = a0, a3 = a0;
    const float* ip = &Ism[ty * 4 * DD];
#pragma unroll 8
    for (int k = 0; k < DD; k++) {
        float4 w4 = *(const float4*)&Wsm[k * DD + tx * 4];
        float i0 = ip[k], i1 = ip[DD + k], i2 = ip[2 * DD + k], i3 = ip[3 * DD + k];
        a0.x = fmaf(i0, w4.x, a0.x); a0.y = fmaf(i0, w4.y, a0.y);
        a0.z = fmaf(i0, w4.z, a0.z); a0.w = fmaf(i0, w4.w, a0.w);
        a1.x = fmaf(i1, w4.x, a1.x); a1.y = fmaf(i1, w4.y, a1.y);
        a1.z = fmaf(i1, w4.z, a1.z); a1.w = fmaf(i1, w4.w, a1.w);
        a2.x = fmaf(i2, w4.x, a2.x); a2.y = fmaf(i2, w4.y, a2.y);
        a2.z = fmaf(i2, w4.z, a2.z); a2.w = fmaf(i2, w4.w, a2.w);
        a3.x = fmaf(i3, w4.x, a3.x); a3.y = fmaf(i3, w4.y, a3.y);
        a3.z = fmaf(i3, w4.z, a3.z); a3.w = fmaf(i3, w4.w, a3.w);
    }
    int gr = row0 + ty * 4;
    if (gr + 0 < NN) *(float4*)&g_hw[(gr + 0) * DD + tx * 4] = a0;
    if (gr + 1 < NN) *(float4*)&g_hw[(gr + 1) * DD + tx * 4] = a1;
    if (gr + 2 < NN) *(float4*)&g_hw[(gr + 2) * DD + tx * 4] = a2;
    if (gr + 3 < NN) *(float4*)&g_hw[(gr + 3) * DD + tx * 4] = a3;
}

__global__ void k_zero_stats() {
    int c = threadIdx.x;
    if (c < 64) { g_colsum[c * 32] = 0.f; g_colsq[c * 32] = 0.f; }
}

// agg[n] = sum_in_edges hw[src]*w + hw[n]*dinv[n]^2 + bias ; fused BN-stat accumulation
__global__ __launch_bounds__(256) void k_agg(const float* __restrict__ bias) {
    __shared__ float s_sum[8][64];
    __shared__ float s_sq[8][64];
    int lane = threadIdx.x & 31;
    int gw = (blockIdx.x * blockDim.x + threadIdx.x) >> 5;
    int nw = (gridDim.x * 256) >> 5;
    float bx = bias[2 * lane], by = bias[2 * lane + 1];
    float sx = 0.f, sy = 0.f, qx = 0.f, qy = 0.f;
    for (int n = gw; n < NN; n += nw) {
        int p0 = g_rowptr[n], p1 = g_rowptr[n + 1];
        float ax = 0.f, ay = 0.f;
        for (int p = p0; p < p1; p++) {
            int2 e = g_csr[p];
            float w = __int_as_float(e.y);
            float2 v = *(const float2*)&g_hw[e.x * DD + 2 * lane];
            ax = fmaf(v.x, w, ax);
            ay = fmaf(v.y, w, ay);
        }
        float di = g_dinv[n];
        float sw = di * di;
        float2 sv = *(const float2*)&g_hw[n * DD + 2 * lane];
        ax = fmaf(sv.x, sw, ax) + bx;
        ay = fmaf(sv.y, sw, ay) + by;
        *(float2*)&g_agg[n * DD + 2 * lane] = make_float2(ax, ay);
        sx += ax; sy += ay; qx += ax * ax; qy += ay * ay;
    }
    int w8 = threadIdx.x >> 5;
    s_sum[w8][2 * lane] = sx;  s_sum[w8][2 * lane + 1] = sy;
    s_sq [w8][2 * lane] = qx;  s_sq [w8][2 * lane + 1] = qy;
    __syncthreads();
    if (threadIdx.x < 64) {
        float t = 0.f, tq = 0.f;
#pragma unroll
        for (int w = 0; w < 8; w++) { t += s_sum[w][threadIdx.x]; tq += s_sq[w][threadIdx.x]; }
        atomicAdd(&g_colsum[threadIdx.x * 32], t);
        atomicAdd(&g_colsq[threadIdx.x * 32], tq);
    }
}

__global__ void k_finalize(const float* __restrict__ gamma, const float* __restrict__ beta) {
    int c = threadIdx.x;
    if (c < 64) {
        float s = g_colsum[c * 32], q = g_colsq[c * 32];
        const float invN = 1.f / (float)NN;
        float mean = s * invN;
        float var  = q * invN - mean * mean;
        float inv  = rsqrtf(var + 1e-5f);
        float a    = gamma[c] * inv;
        g_scaleA[c] = a;
        g_shiftB[c] = beta[c] - mean * a;
    }
}

__global__ void k_out(float* __restrict__ out) {
    int i = blockIdx.x * blockDim.x + threadIdx.x;
    if (i < NN * DD) {
        int c = i & 63;
        out[i] = fmaxf(fmaf(g_agg[i], g_scaleA[c], g_shiftB[c]), 0.f);
    }
}

// ---------------- launch ----------------
extern "C" void kernel_launch(void* const* d_in, const int* in_sizes, int n_in,
                              void* d_out, int out_size) {
    const float* x   = (const float*)d_in[0];
    const void*  ei  = d_in[1];                 // int32 or int64; detected on device
    const float* Ws  = (const float*)d_in[2];
    const float* bs  = (const float*)d_in[3];
    const float* gms = (const float*)d_in[4];
    const float* bts = (const float*)d_in[5];

    k_detect<<<1, 256>>>((const int*)ei);
    k_zero_counts<<<(NN + 255) / 256, 256>>>();
    k_degree<<<(NE + 255) / 256, 256>>>(ei);
    k_dinv<<<(NN + 255) / 256, 256>>>();
    k_scan1<<<NB_SCAN, 1024>>>();
    k_scan2<<<1, 128>>>();
    k_scan3<<<NB_SCAN, 1024>>>();
    k_rowptr_end<<<1, 1>>>();
    k_fill<<<(NE + 255) / 256, 256>>>(ei);

    for (int l = 0; l < 4; l++) {
        k_gemm<<<(NN + 63) / 64, 256>>>(x, Ws + l * DD * DD, l);
        k_zero_stats<<<1, 64>>>();
        k_agg<<<1480, 256>>>(bs + l * DD);
        k_finalize<<<1, 64>>>(gms + l * DD, bts + l * DD);
    }
    k_out<<<(NN * DD + 255) / 256, 256>>>((float*)d_out);
}